// round 16
// baseline (speedup 1.0000x reference)
#include <cuda_runtime.h>
#include <cuda_fp16.h>
#include <math.h>
#include <stdint.h>

// ---------------------------------------------------------------------------
// DeBERTa layer, fp16 mma.sync m16n8k16 (fp32 accumulate), ldmatrix fragment
// loads. Uniform K-contiguous layout (A m-major, B n-major): B's mma fragment
// is the plain (non-transposed) ldmatrix of our n-major storage.
// Strides to gemm_h are HALF units. B=16 S=512 H=768 NH=12 DH=64 P=512 I=3072.
// ---------------------------------------------------------------------------

constexpr int kB  = 16;
constexpr int kS  = 512;
constexpr int kH  = 768;
constexpr int kNH = 12;
constexpr int kDH = 64;
constexpr int kP  = 512;
constexpr int kI  = 3072;
constexpr int kBS = kB * kS;
constexpr int kBH = kB * kNH;
constexpr float kScale = 0.07216878364870322f;

constexpr size_t SZ_QKV = (size_t)kBH * kS * kDH;
constexpr size_t SZ_POS = (size_t)kNH * 2 * kP * kDH;
constexpr size_t SZ_CP  = (size_t)kBH * kS * 2 * kP;
constexpr size_t SZ_W   = (size_t)kH * kH;
constexpr size_t SZ_W1  = (size_t)kH * kI;

constexpr size_t OFF_Q    = 0;
constexpr size_t OFF_K    = OFF_Q + SZ_QKV;
constexpr size_t OFF_V    = OFF_K + SZ_QKV;          // V^T layout [z][d][s]
constexpr size_t OFF_PK   = OFF_V + SZ_QKV;
constexpr size_t OFF_PQ   = OFF_PK + SZ_POS;
constexpr size_t OFF_C2P  = OFF_PQ + SZ_POS;
constexpr size_t OFF_P2C  = OFF_C2P + SZ_CP;
constexpr size_t OFF_CTX  = OFF_P2C + SZ_CP;
constexpr size_t OFF_T1   = OFF_CTX + SZ_QKV;        // fp32
constexpr size_t OFF_H1   = OFF_T1 + SZ_QKV;         // fp32 residual
constexpr size_t OFF_H1R  = OFF_H1 + SZ_QKV;         // half (FFN1 A)
constexpr size_t OFF_F1   = OFF_C2P;                 // alias, half
constexpr size_t OFF_CHS  = OFF_H1R + SZ_QKV;        // half
constexpr size_t OFF_CPE  = OFF_CHS + SZ_QKV;        // half
constexpr size_t OFF_CWQ  = OFF_CPE + SZ_POS;        // WT [N][K] half
constexpr size_t OFF_CWK  = OFF_CWQ + SZ_W;
constexpr size_t OFF_CWV  = OFF_CWK + SZ_W;
constexpr size_t OFF_CWPK = OFF_CWV + SZ_W;
constexpr size_t OFF_CWPQ = OFF_CWPK + SZ_W;
constexpr size_t OFF_CWO  = OFF_CWPQ + SZ_W;
constexpr size_t OFF_CW1  = OFF_CWO + SZ_W;
constexpr size_t OFF_CW2  = OFF_CW1 + SZ_W1;
constexpr size_t OFF_CB   = OFF_CW2 + SZ_W1;         // fp32 biases
constexpr size_t TOTAL    = OFF_CB + 3 * kH;

__device__ __align__(256) float g_scratch[TOTAL];

enum { EPI_NONE = 0, EPI_GELU = 1, EPI_QKV = 2, EPI_POS = 3 };
constexpr size_t NOBIAS = (size_t)-1;

__device__ __forceinline__ void mma_f16(float (&d)[4], const uint32_t (&a)[4],
                                        const uint32_t (&b)[2]) {
    asm volatile(
        "mma.sync.aligned.m16n8k16.row.col.f32.f16.f16.f32 "
        "{%0,%1,%2,%3}, {%4,%5,%6,%7}, {%8,%9}, {%0,%1,%2,%3};"
        : "+f"(d[0]), "+f"(d[1]), "+f"(d[2]), "+f"(d[3])
        : "r"(a[0]), "r"(a[1]), "r"(a[2]), "r"(a[3]), "r"(b[0]), "r"(b[1]));
}
__device__ __forceinline__ void ldm_x4(uint32_t (&r)[4], uint32_t addr) {
    asm volatile(
        "ldmatrix.sync.aligned.m8n8.x4.shared.b16 {%0,%1,%2,%3}, [%4];"
        : "=r"(r[0]), "=r"(r[1]), "=r"(r[2]), "=r"(r[3]) : "r"(addr));
}
__device__ __forceinline__ void cp_async16(uint32_t s, const void* g) {
    asm volatile("cp.async.cg.shared.global [%0], [%1], 16;" :: "r"(s), "l"(g));
}
__device__ __forceinline__ void cp_commit() {
    asm volatile("cp.async.commit_group;" ::: "memory");
}
__device__ __forceinline__ void cp_wait1() {
    asm volatile("cp.async.wait_group 1;" ::: "memory");
}
__device__ __forceinline__ void cp_wait0() {
    asm volatile("cp.async.wait_group 0;" ::: "memory");
}
__device__ __forceinline__ uint32_t smem_u32(const void* p) {
    return (uint32_t)__cvta_generic_to_shared(p);
}

// ---------------------------------------------------------------------------
// preconvert: hs/pe -> half; biases contiguous fp32.
// ---------------------------------------------------------------------------
constexpr size_t F4_HS = SZ_QKV / 4;
constexpr size_t F4_PE = SZ_POS / 4;
constexpr size_t F4_TOTAL = F4_HS + F4_PE;

__global__ __launch_bounds__(256)
void preconvert_kernel(const float* __restrict__ hs, const float* __restrict__ pe,
                       const float* __restrict__ bq, const float* __restrict__ bk,
                       const float* __restrict__ bv)
{
    size_t i = (size_t)blockIdx.x * 256 + threadIdx.x;
    if (i < 576) {
        float4* cb = reinterpret_cast<float4*>(g_scratch + OFF_CB);
        if (i < 192)      cb[i] = reinterpret_cast<const float4*>(bq)[i];
        else if (i < 384) cb[i] = reinterpret_cast<const float4*>(bk)[i - 192];
        else              cb[i] = reinterpret_cast<const float4*>(bv)[i - 384];
    }
    if (i >= F4_TOTAL) return;
    const float* src; __half2* dst;
    if (i < F4_HS) { src = hs; dst = reinterpret_cast<__half2*>(g_scratch + OFF_CHS); }
    else { i -= F4_HS; src = pe; dst = reinterpret_cast<__half2*>(g_scratch + OFF_CPE); }
    const float4 v = reinterpret_cast<const float4*>(src)[i];
    dst[i * 2]     = __floats2half2_rn(v.x, v.y);
    dst[i * 2 + 1] = __floats2half2_rn(v.z, v.w);
}

// ---------------------------------------------------------------------------
// transpose weights W[K,N] -> WT[N,K] half. 8064 flat 32x32 tiles.
// ---------------------------------------------------------------------------
__global__ __launch_bounds__(256)
void transpose_kernel(const float* __restrict__ Wq, const float* __restrict__ Wk,
                      const float* __restrict__ Wv, const float* __restrict__ Wpk,
                      const float* __restrict__ Wpq, const float* __restrict__ Wo,
                      const float* __restrict__ W1, const float* __restrict__ W2)
{
    int bid = blockIdx.x;
    const float* src; __half* dst; int R, C, t;
    if (bid < 3456) {
        const float* ws[6] = {Wq, Wk, Wv, Wpk, Wpq, Wo};
        const size_t od[6] = {OFF_CWQ, OFF_CWK, OFF_CWV, OFF_CWPK, OFF_CWPQ, OFF_CWO};
        src = ws[bid / 576]; dst = reinterpret_cast<__half*>(g_scratch + od[bid / 576]);
        R = kH; C = kH; t = bid % 576;
    } else if (bid < 5760) {
        src = W1; dst = reinterpret_cast<__half*>(g_scratch + OFF_CW1);
        R = kH; C = kI; t = bid - 3456;
    } else {
        src = W2; dst = reinterpret_cast<__half*>(g_scratch + OFF_CW2);
        R = kI; C = kH; t = bid - 5760;
    }
    const int n0 = (t % (C / 32)) * 32, k0 = (t / (C / 32)) * 32;
    __shared__ float tl[32][33];
    const int tx = threadIdx.x & 31, ty = threadIdx.x >> 5;
#pragma unroll
    for (int r = ty; r < 32; r += 8)
        tl[r][tx] = src[(size_t)(k0 + r) * C + n0 + tx];
    __syncthreads();
#pragma unroll
    for (int r = ty; r < 32; r += 8)
        dst[(size_t)(n0 + r) * R + k0 + tx] = __float2half_rn(tl[tx][r]);
}

// ---------------------------------------------------------------------------
// Dense fp16 GEMM, ldmatrix fragments. 128x128 tile, BK=32 halves, 3-stage
// cp.async ring, 8 warps 4x2 (warp tile 32x64). bStride/cStride HALF units.
// ---------------------------------------------------------------------------
constexpr int GH_HW  = 20;
constexpr int GH_STG = 128 * GH_HW;
constexpr int GH_SMEM = 6 * GH_STG * 4;

template<int EPI>
__global__ __launch_bounds__(256, 2)
void gemm_h(size_t aOff, size_t bOff, size_t bStride,
            const float* __restrict__ biasEx, size_t biasOff, size_t biasStride,
            size_t cOff, size_t cStride, int K, int Ntot)
{
    extern __shared__ __align__(16) uint32_t dsm[];
    uint32_t* As = dsm;
    uint32_t* Bs = dsm + 3 * GH_STG;

    const int z = blockIdx.z;
    const int m0 = blockIdx.y * 128, n0 = blockIdx.x * 128;
    const int tid = threadIdx.x, warp = tid >> 5, lane = tid & 31;
    const int wm = warp & 3, wn = warp >> 2;
    const int mBase = wm * 32, nBase = wn * 64;
    const int gi = lane >> 2, gj = lane & 3;

    const __half* Ah = reinterpret_cast<const __half*>(g_scratch + aOff)
                     + (size_t)m0 * K;
    const __half* Bh = reinterpret_cast<const __half*>(g_scratch + bOff)
                     + (size_t)z * bStride + (size_t)n0 * K;
    const uint32_t sA = smem_u32(As), sB = smem_u32(Bs);

    // ldmatrix per-thread row bases (word units, stage/kk added later)
    const int matIdx = lane >> 3, rowIn = lane & 7;
    int aLdm[2], bLdm[4];
#pragma unroll
    for (int mt = 0; mt < 2; mt++)
        aLdm[mt] = (mBase + mt * 16 + (matIdx & 1) * 8 + rowIn) * GH_HW
                 + (matIdx >> 1) * 4;
#pragma unroll
    for (int p = 0; p < 4; p++)
        bLdm[p] = (nBase + (2 * p + (matIdx >> 1)) * 8 + rowIn) * GH_HW
                + (matIdx & 1) * 4;

    auto load_stage = [&](int st, int kblk) {
#pragma unroll
        for (int i = 0; i < 2; i++) {
            const int idx = tid + i * 256;
            const int row = idx >> 2, g = idx & 3;
            cp_async16(sA + (uint32_t)(st * GH_STG + row * GH_HW + g * 4) * 4,
                       Ah + (size_t)row * K + kblk + g * 8);
            cp_async16(sB + (uint32_t)(st * GH_STG + row * GH_HW + g * 4) * 4,
                       Bh + (size_t)row * K + kblk + g * 8);
        }
    };

    float acc[2][8][4];
#pragma unroll
    for (int i = 0; i < 2; i++)
#pragma unroll
        for (int j = 0; j < 8; j++)
#pragma unroll
            for (int r = 0; r < 4; r++) acc[i][j][r] = 0.f;

    const int NC = K / 32;
    load_stage(0, 0);  cp_commit();
    load_stage(1, 32); cp_commit();

    for (int c = 0; c < NC; c++) {
        cp_wait1();
        __syncthreads();
        if (c + 2 < NC) load_stage((c + 2) % 3, (c + 2) * 32);
        cp_commit();
        const uint32_t stW = (uint32_t)((c % 3) * GH_STG);
#pragma unroll
        for (int ks = 0; ks < 2; ks++) {
            const int kk = ks * 8;
            uint32_t af[2][4], bq[4][4];
            ldm_x4(af[0], sA + (stW + aLdm[0] + kk) * 4);
            ldm_x4(af[1], sA + (stW + aLdm[1] + kk) * 4);
#pragma unroll
            for (int p = 0; p < 4; p++)
                ldm_x4(bq[p], sB + (stW + bLdm[p] + kk) * 4);
#pragma unroll
            for (int mt = 0; mt < 2; mt++)
#pragma unroll
                for (int nt = 0; nt < 8; nt++) {
                    const uint32_t bf[2] = { bq[nt >> 1][(nt & 1) * 2 + 0],
                                             bq[nt >> 1][(nt & 1) * 2 + 1] };
                    mma_f16(acc[mt][nt], af[mt], bf);
                }
        }
    }

    const float* bias = biasEx ? biasEx
                      : (biasOff != NOBIAS ? (const float*)g_scratch + biasOff
                                           : nullptr);
    if (bias) bias += (size_t)z * biasStride;
#pragma unroll
    for (int mt = 0; mt < 2; mt++)
#pragma unroll
        for (int nt = 0; nt < 8; nt++)
#pragma unroll
            for (int hf = 0; hf < 2; hf++) {
                const int m = m0 + mBase + mt * 16 + gi + hf * 8;
                const int n = n0 + nBase + nt * 8 + 2 * gj;
                float v0 = acc[mt][nt][hf * 2 + 0];
                float v1 = acc[mt][nt][hf * 2 + 1];
                if (bias) { v0 += bias[n]; v1 += bias[n + 1]; }
                if constexpr (EPI == EPI_GELU) {
                    v0 = 0.5f * v0 * (1.f + erff(v0 * 0.70710678118654752f));
                    v1 = 0.5f * v1 * (1.f + erff(v1 * 0.70710678118654752f));
                }
                if constexpr (EPI == EPI_NONE) {
                    float* Cf = g_scratch + cOff;
                    *reinterpret_cast<float2*>(&Cf[(size_t)m * Ntot + n]) =
                        make_float2(v0, v1);
                } else {
                    __half* Ch = reinterpret_cast<__half*>(g_scratch + cOff);
                    if constexpr (EPI == EPI_GELU) {
                        *reinterpret_cast<__half2*>(&Ch[(size_t)m * Ntot + n]) =
                            __floats2half2_rn(v0, v1);
                    } else if constexpr (EPI == EPI_QKV) {
                        const int bb = m >> 9, s = m & 511, h = n >> 6, d = n & 63;
                        if (z < 2) {
                            *reinterpret_cast<__half2*>(
                                &Ch[(size_t)z * cStride
                                    + ((size_t)(bb * kNH + h) * kS + s) * kDH + d]) =
                                __floats2half2_rn(v0, v1);
                        } else {   // V^T: [bh][d][s]
                            __half* Vt = Ch + 2 * cStride
                                       + ((size_t)(bb * kNH + h) * kDH + d) * kS + s;
                            Vt[0]  = __float2half_rn(v0);
                            Vt[kS] = __float2half_rn(v1);
                        }
                    } else {       // EPI_POS
                        const int h = n >> 6, d = n & 63;
                        *reinterpret_cast<__half2*>(
                            &Ch[(size_t)z * cStride
                                + ((size_t)h * (2 * kP) + m) * kDH + d]) =
                            __floats2half2_rn(v0, v1);
                    }
                }
            }
}

// ---------------------------------------------------------------------------
// Band GEMM fp16, ldmatrix fragments: diagonal 128x128 tiles, K=64.
// ---------------------------------------------------------------------------
constexpr int BH_HW = 36;

__global__ __launch_bounds__(256, 2)
void band_gemm_h(size_t aOff, size_t bOff, size_t cOff,
                 size_t aStride, size_t bStride, size_t cStride)
{
    __shared__ __align__(16) uint32_t As[128 * BH_HW], Bs[128 * BH_HW];
    const int z = blockIdx.z;
    const __half* Ah = reinterpret_cast<const __half*>(g_scratch + aOff)
                     + (size_t)z * aStride;
    const __half* Bh = reinterpret_cast<const __half*>(g_scratch + bOff)
                     + (size_t)(z % kNH) * bStride;
    __half* Ch = reinterpret_cast<__half*>(g_scratch + cOff) + (size_t)z * cStride;

    const int m0 = blockIdx.y * 128;
    const int n0 = blockIdx.y * 128 + blockIdx.x * 128;
    const int tid = threadIdx.x, warp = tid >> 5, lane = tid & 31;
    const int wm = warp & 3, wn = warp >> 2;
    const int mBase = wm * 32, nBase = wn * 64;
    const int gi = lane >> 2, gj = lane & 3;
    const uint32_t sA = smem_u32(As), sB = smem_u32(Bs);

    const int matIdx = lane >> 3, rowIn = lane & 7;
    int aLdm[2], bLdm[4];
#pragma unroll
    for (int mt = 0; mt < 2; mt++)
        aLdm[mt] = (mBase + mt * 16 + (matIdx & 1) * 8 + rowIn) * BH_HW
                 + (matIdx >> 1) * 4;
#pragma unroll
    for (int p = 0; p < 4; p++)
        bLdm[p] = (nBase + (2 * p + (matIdx >> 1)) * 8 + rowIn) * BH_HW
                + (matIdx & 1) * 4;

#pragma unroll
    for (int i = 0; i < 4; i++) {
        const int idx = tid + i * 256;
        const int row = idx >> 3, g = idx & 7;
        cp_async16(sA + (uint32_t)(row * BH_HW + g * 4) * 4,
                   Ah + (size_t)(m0 + row) * kDH + g * 8);
        cp_async16(sB + (uint32_t)(row * BH_HW + g * 4) * 4,
                   Bh + (size_t)(n0 + row) * kDH + g * 8);
    }
    cp_commit();
    cp_wait0();
    __syncthreads();

    float acc[2][8][4];
#pragma unroll
    for (int i = 0; i < 2; i++)
#pragma unroll
        for (int j = 0; j < 8; j++)
#pragma unroll
            for (int r = 0; r < 4; r++) acc[i][j][r] = 0.f;

#pragma unroll
    for (int ks = 0; ks < 4; ks++) {
        const int kk = ks * 8;
        uint32_t af[2][4], bq[4][4];
        ldm_x4(af[0], sA + (uint32_t)(aLdm[0] + kk) * 4);
        ldm_x4(af[1], sA + (uint32_t)(aLdm[1] + kk) * 4);
#pragma unroll
        for (int p = 0; p < 4; p++)
            ldm_x4(bq[p], sB + (uint32_t)(bLdm[p] + kk) * 4);
#pragma unroll
        for (int mt = 0; mt < 2; mt++)
#pragma unroll
            for (int nt = 0; nt < 8; nt++) {
                const uint32_t bf[2] = { bq[nt >> 1][(nt & 1) * 2 + 0],
                                         bq[nt >> 1][(nt & 1) * 2 + 1] };
                mma_f16(acc[mt][nt], af[mt], bf);
            }
    }
#pragma unroll
    for (int mt = 0; mt < 2; mt++)
#pragma unroll
        for (int nt = 0; nt < 8; nt++)
#pragma unroll
            for (int hf = 0; hf < 2; hf++) {
                const int m = m0 + mBase + mt * 16 + gi + hf * 8;
                const int n = n0 + nBase + nt * 8 + 2 * gj;
                *reinterpret_cast<__half2*>(&Ch[(size_t)m * (2 * kP) + n]) =
                    __floats2half2_rn(acc[mt][nt][hf * 2 + 0],
                                      acc[mt][nt][hf * 2 + 1]);
            }
}

// ---------------------------------------------------------------------------
// Flash attention fp16 with ldmatrix fragments (numerics unchanged).
// ---------------------------------------------------------------------------
constexpr int FH_QS = 0;
constexpr int FH_KS = 128 * 36;
constexpr int FH_VS = 2 * 128 * 36;
constexpr int FH_PG = FH_VS + 64 * 68;
constexpr int FA_SMEM = (FH_PG + 128 * 132) * 4;

__global__ __launch_bounds__(256, 1)
void flash_attn_kernel(const float* __restrict__ mask)
{
    extern __shared__ __align__(16) uint32_t fsm[];
    uint32_t* Qs = fsm + FH_QS;
    uint32_t* Ks = fsm + FH_KS;
    uint32_t* Vs = fsm + FH_VS;
    float*    Pg = reinterpret_cast<float*>(fsm + FH_PG);
    uint32_t* Pp = fsm + FH_PG;

    const int z  = blockIdx.y;
    const int i0 = blockIdx.x * 128;
    const int tid = threadIdx.x, warp = tid >> 5, lane = tid & 31;
    const int gi = lane >> 2, gj = lane & 3;
    const int mBase = warp * 16;

    const __half* Qh = reinterpret_cast<const __half*>(g_scratch + OFF_Q)
                     + (size_t)z * kS * kDH;
    const __half* Kh = reinterpret_cast<const __half*>(g_scratch + OFF_K)
                     + (size_t)z * kS * kDH;
    const __half* Vth = reinterpret_cast<const __half*>(g_scratch + OFF_V)
                      + (size_t)z * kDH * kS;
    const __half* C2Ph = reinterpret_cast<const __half*>(g_scratch + OFF_C2P)
                       + (size_t)z * kS * (2 * kP);
    const __half* P2Ch = reinterpret_cast<const __half*>(g_scratch + OFF_P2C)
                       + (size_t)z * kS * (2 * kP);
    const float* mrow = mask + (size_t)(z / kNH) * kS;

    const uint32_t sQ = smem_u32(Qs), sK = smem_u32(Ks);
    const uint32_t sV = smem_u32(Vs), sP = smem_u32(Pp);
    const int matIdx = lane >> 3, rowIn = lane & 7;
    const int qLdm = (mBase + (matIdx & 1) * 8 + rowIn) * 36 + (matIdx >> 1) * 4;
    const int pLdm = (mBase + (matIdx & 1) * 8 + rowIn) * 68 + (matIdx >> 1) * 4;
    int kLdm[8], vLdm[4];
#pragma unroll
    for (int p = 0; p < 8; p++)
        kLdm[p] = ((2 * p + (matIdx >> 1)) * 8 + rowIn) * 36 + (matIdx & 1) * 4;
#pragma unroll
    for (int p = 0; p < 4; p++)
        vLdm[p] = ((2 * p + (matIdx >> 1)) * 8 + rowIn) * 68 + (matIdx & 1) * 4;

#pragma unroll
    for (int r = 0; r < 4; r++) {
        const int idx = tid + r * 256;
        const int row = idx >> 3, g = idx & 7;
        *reinterpret_cast<uint4*>(&Qs[row * 36 + g * 4]) =
            *reinterpret_cast<const uint4*>(Qh + (size_t)(i0 + row) * kDH + g * 8);
    }

    float ctx[8][4];
#pragma unroll
    for (int n = 0; n < 8; n++)
#pragma unroll
        for (int c = 0; c < 4; c++) ctx[n][c] = 0.f;
    float rm[2] = {-1e30f, -1e30f};
    float rs[2] = {0.f, 0.f};

    for (int jt = 0; jt < 4; jt++) {
        const int j0 = jt * 128;
        __syncthreads();
#pragma unroll
        for (int r = 0; r < 4; r++) {
            const int idx = tid + r * 256;
            const int row = idx >> 3, g = idx & 7;
            *reinterpret_cast<uint4*>(&Ks[row * 36 + g * 4]) =
                *reinterpret_cast<const uint4*>(Kh + (size_t)(j0 + row) * kDH + g * 8);
        }
#pragma unroll
        for (int r = 0; r < 4; r++) {
            const int idx = tid + r * 256;
            const int row = idx >> 4, g = idx & 15;
            *reinterpret_cast<uint4*>(&Vs[row * 68 + g * 4]) =
                *reinterpret_cast<const uint4*>(Vth + (size_t)row * kS + j0 + g * 8);
        }
        __syncthreads();

        // ---- S = Q @ K^T : warp 16x128, K=64 -> 4 k16 steps ----
        float accS[16][4];
#pragma unroll
        for (int n = 0; n < 16; n++)
#pragma unroll
            for (int c = 0; c < 4; c++) accS[n][c] = 0.f;
#pragma unroll
        for (int ks = 0; ks < 4; ks++) {
            const int kk = ks * 8;
            uint32_t af[4], bq[8][4];
            ldm_x4(af, sQ + (uint32_t)(qLdm + kk) * 4);
#pragma unroll
            for (int p = 0; p < 8; p++)
                ldm_x4(bq[p], sK + (uint32_t)(kLdm[p] + kk) * 4);
#pragma unroll
            for (int nt = 0; nt < 16; nt++) {
                const uint32_t bf[2] = { bq[nt >> 1][(nt & 1) * 2 + 0],
                                         bq[nt >> 1][(nt & 1) * 2 + 1] };
                mma_f16(accS[nt], af, bf);
            }
        }

        // p2c gather stage
#pragma unroll
        for (int r = 0; r < 64; r++) {
            const int idx = tid + r * 256;
            const int jl = idx >> 7, il = idx & 127;
            Pg[jl * 132 + il] = __half2float(
                P2Ch[(size_t)(j0 + jl) * (2 * kP) + (j0 + jl) - (i0 + il) + kP]);
        }
        __syncthreads();
#pragma unroll
        for (int nt = 0; nt < 16; nt++)
#pragma unroll
            for (int hf = 0; hf < 2; hf++) {
                const int il = mBase + gi + hf * 8;
                const int jl = nt * 8 + 2 * gj;
                accS[nt][hf * 2 + 0] += Pg[jl * 132 + il];
                accS[nt][hf * 2 + 1] += Pg[(jl + 1) * 132 + il];
            }
        __syncthreads();
        // c2p gather stage
#pragma unroll
        for (int r = 0; r < 64; r++) {
            const int idx = tid + r * 256;
            const int il = idx >> 7, jl = idx & 127;
            Pg[il * 132 + jl] = __half2float(
                C2Ph[(size_t)(i0 + il) * (2 * kP) + (i0 + il) - (j0 + jl) + kP]);
        }
        __syncthreads();
#pragma unroll
        for (int nt = 0; nt < 16; nt++)
#pragma unroll
            for (int hf = 0; hf < 2; hf++) {
                const int il = mBase + gi + hf * 8;
                const int jl = nt * 8 + 2 * gj;
                float s0 = (accS[nt][hf * 2 + 0] + Pg[il * 132 + jl]) * kScale;
                float s1 = (accS[nt][hf * 2 + 1] + Pg[il * 132 + jl + 1]) * kScale;
                if (mrow[j0 + jl] <= 0.f)     s0 = -1e9f;
                if (mrow[j0 + jl + 1] <= 0.f) s1 = -1e9f;
                accS[nt][hf * 2 + 0] = s0;
                accS[nt][hf * 2 + 1] = s1;
            }

        // online softmax (rows warp-local, quad shuffles)
#pragma unroll
        for (int hf = 0; hf < 2; hf++) {
            float tmax = -1e30f;
#pragma unroll
            for (int nt = 0; nt < 16; nt++)
                tmax = fmaxf(tmax, fmaxf(accS[nt][hf * 2], accS[nt][hf * 2 + 1]));
            tmax = fmaxf(tmax, __shfl_xor_sync(0xFFFFFFFFu, tmax, 1));
            tmax = fmaxf(tmax, __shfl_xor_sync(0xFFFFFFFFu, tmax, 2));
            const float mNew = fmaxf(rm[hf], tmax);
            const float alpha = __expf(rm[hf] - mNew);
            float lsum = 0.f;
#pragma unroll
            for (int nt = 0; nt < 16; nt++) {
                const float e0 = __expf(accS[nt][hf * 2 + 0] - mNew);
                const float e1 = __expf(accS[nt][hf * 2 + 1] - mNew);
                accS[nt][hf * 2 + 0] = e0;
                accS[nt][hf * 2 + 1] = e1;
                lsum += e0 + e1;
            }
            lsum += __shfl_xor_sync(0xFFFFFFFFu, lsum, 1);
            lsum += __shfl_xor_sync(0xFFFFFFFFu, lsum, 2);
            rs[hf] = rs[hf] * alpha + lsum;
            rm[hf] = mNew;
#pragma unroll
            for (int n = 0; n < 8; n++) {
                ctx[n][hf * 2 + 0] *= alpha;
                ctx[n][hf * 2 + 1] *= alpha;
            }
        }

        __syncthreads();
        // write P as half words, m-major [il][68 words]
#pragma unroll
        for (int nt = 0; nt < 16; nt++)
#pragma unroll
            for (int hf = 0; hf < 2; hf++) {
                const int il = mBase + gi + hf * 8;
                const __half2 p = __floats2half2_rn(accS[nt][hf * 2 + 0],
                                                    accS[nt][hf * 2 + 1]);
                Pp[il * 68 + nt * 4 + gj] = *reinterpret_cast<const uint32_t*>(&p);
            }
        __syncthreads();

        // ---- ctx += P @ V : K=128 halves -> 8 k16 steps ----
#pragma unroll
        for (int ks = 0; ks < 8; ks++) {
            const int kk = ks * 8;
            uint32_t af[4], bq[4][4];
            ldm_x4(af, sP + (uint32_t)(pLdm + kk) * 4);
#pragma unroll
            for (int p = 0; p < 4; p++)
                ldm_x4(bq[p], sV + (uint32_t)(vLdm[p] + kk) * 4);
#pragma unroll
            for (int nt = 0; nt < 8; nt++) {
                const uint32_t bf[2] = { bq[nt >> 1][(nt & 1) * 2 + 0],
                                         bq[nt >> 1][(nt & 1) * 2 + 1] };
                mma_f16(ctx[nt], af, bf);
            }
        }
    }

    const int bb = z / kNH, h = z % kNH;
    const float inv0 = 1.f / rs[0], inv1 = 1.f / rs[1];
    __half* Cg = reinterpret_cast<__half*>(g_scratch + OFF_CTX);
#pragma unroll
    for (int nt = 0; nt < 8; nt++)
#pragma unroll
        for (int hf = 0; hf < 2; hf++) {
            const int m = i0 + mBase + gi + hf * 8;
            const int d = nt * 8 + 2 * gj;
            const float inv = hf ? inv1 : inv0;
            *reinterpret_cast<__half2*>(
                &Cg[((size_t)bb * kS + m) * kH + h * kDH + d]) =
                __floats2half2_rn(ctx[nt][hf * 2 + 0] * inv,
                                  ctx[nt][hf * 2 + 1] * inv);
        }
}

// ---------------------------------------------------------------------------
// out = LayerNorm(X + Y) * g + b; optional half copy for next GEMM.
// ---------------------------------------------------------------------------
__global__ void add_ln_kernel(const float* __restrict__ Xex, size_t xOff, size_t yOff,
                              const float* __restrict__ g, const float* __restrict__ bb,
                              float* __restrict__ outEx, size_t outOff,
                              int makeHalf, size_t rOff)
{
    const float* X = Xex ? Xex : (const float*)g_scratch + xOff;
    const float* Y = (const float*)g_scratch + yOff;
    float* O = outEx ? outEx : g_scratch + outOff;

    const size_t off = (size_t)blockIdx.x * kH;
    const int t = threadIdx.x;
    const float v0 = X[off + t]       + Y[off + t];
    const float v1 = X[off + t + 256] + Y[off + t + 256];
    const float v2 = X[off + t + 512] + Y[off + t + 512];

    __shared__ float red[256];
    red[t] = v0 + v1 + v2;
    __syncthreads();
    for (int s = 128; s > 0; s >>= 1) {
        if (t < s) red[t] += red[t + s];
        __syncthreads();
    }
    const float mean = red[0] * (1.f / 768.f);
    __syncthreads();
    const float d0 = v0 - mean, d1 = v1 - mean, d2 = v2 - mean;
    red[t] = d0 * d0 + d1 * d1 + d2 * d2;
    __syncthreads();
    for (int s = 128; s > 0; s >>= 1) {
        if (t < s) red[t] += red[t + s];
        __syncthreads();
    }
    const float rstd = rsqrtf(red[0] * (1.f / 768.f) + 1e-7f);

    const float o0 = d0 * rstd * g[t]       + bb[t];
    const float o1 = d1 * rstd * g[t + 256] + bb[t + 256];
    const float o2 = d2 * rstd * g[t + 512] + bb[t + 512];
    O[off + t]       = o0;
    O[off + t + 256] = o1;
    O[off + t + 512] = o2;
    if (makeHalf) {
        __half* R = reinterpret_cast<__half*>(g_scratch + rOff);
        R[off + t]       = __float2half_rn(o0);
        R[off + t + 256] = __float2half_rn(o1);
        R[off + t + 512] = __float2half_rn(o2);
    }
}

// ---------------------------------------------------------------------------
extern "C" void kernel_launch(void* const* d_in, const int* in_sizes, int n_in,
                              void* d_out, int out_size)
{
    const float* hs  = (const float*)d_in[0];
    const float* am  = (const float*)d_in[1];
    const float* pe  = (const float*)d_in[2];
    const float* Wq  = (const float*)d_in[3];
    const float* bq  = (const float*)d_in[4];
    const float* Wk  = (const float*)d_in[5];
    const float* bk  = (const float*)d_in[6];
    const float* Wv  = (const float*)d_in[7];
    const float* bv  = (const float*)d_in[8];
    const float* Wpk = (const float*)d_in[9];
    const float* Wpq = (const float*)d_in[10];
    const float* Wo  = (const float*)d_in[11];
    const float* bo  = (const float*)d_in[12];
    const float* g1  = (const float*)d_in[13];
    const float* be1 = (const float*)d_in[14];
    const float* W1  = (const float*)d_in[15];
    const float* b1  = (const float*)d_in[16];
    const float* W2  = (const float*)d_in[17];
    const float* b2  = (const float*)d_in[18];
    const float* g2  = (const float*)d_in[19];
    const float* be2 = (const float*)d_in[20];
    float* out = (float*)d_out;

    auto qkvK = gemm_h<EPI_QKV>;
    auto posK = gemm_h<EPI_POS>;
    auto nnK  = gemm_h<EPI_NONE>;
    auto gelK = gemm_h<EPI_GELU>;
    cudaFuncSetAttribute((const void*)qkvK, cudaFuncAttributeMaxDynamicSharedMemorySize, GH_SMEM);
    cudaFuncSetAttribute((const void*)posK, cudaFuncAttributeMaxDynamicSharedMemorySize, GH_SMEM);
    cudaFuncSetAttribute((const void*)nnK,  cudaFuncAttributeMaxDynamicSharedMemorySize, GH_SMEM);
    cudaFuncSetAttribute((const void*)gelK, cudaFuncAttributeMaxDynamicSharedMemorySize, GH_SMEM);
    cudaFuncSetAttribute((const void*)flash_attn_kernel,
                         cudaFuncAttributeMaxDynamicSharedMemorySize, FA_SMEM);

    preconvert_kernel<<<(int)((F4_TOTAL + 255) / 256), 256>>>(hs, pe, bq, bk, bv);
    transpose_kernel<<<8064, 256>>>(Wq, Wk, Wv, Wpk, Wpq, Wo, W1, W2);

    // QKV: z strides in HALF units
    qkvK<<<dim3(kH / 128, kBS / 128, 3), 256, GH_SMEM>>>(
        OFF_CHS, OFF_CWQ, 2 * SZ_W, nullptr, OFF_CB, kH, OFF_Q, 2 * SZ_QKV, kH, kH);
    posK<<<dim3(kH / 128, (2 * kP) / 128, 2), 256, GH_SMEM>>>(
        OFF_CPE, OFF_CWPK, 2 * SZ_W, nullptr, NOBIAS, 0, OFF_PK, 2 * SZ_POS, kH, kH);

    band_gemm_h<<<dim3(5, kS / 128, kBH), 256>>>(
        OFF_Q, OFF_PK, OFF_C2P,
        (size_t)kS * kDH, (size_t)(2 * kP) * kDH, (size_t)kS * (2 * kP));
    band_gemm_h<<<dim3(5, kS / 128, kBH), 256>>>(
        OFF_K, OFF_PQ, OFF_P2C,
        (size_t)kS * kDH, (size_t)(2 * kP) * kDH, (size_t)kS * (2 * kP));

    flash_attn_kernel<<<dim3(kS / 128, kBH), 256, FA_SMEM>>>(am);

    nnK<<<dim3(kH / 128, kBS / 128, 1), 256, GH_SMEM>>>(
        OFF_CTX, OFF_CWO, 0, bo, NOBIAS, 0, OFF_T1, 0, kH, kH);
    add_ln_kernel<<<kBS, 256>>>(hs, 0, OFF_T1, g1, be1, nullptr, OFF_H1, 1, OFF_H1R);

    gelK<<<dim3(kI / 128, kBS / 128, 1), 256, GH_SMEM>>>(
        OFF_H1R, OFF_CW1, 0, b1, NOBIAS, 0, OFF_F1, 0, kH, kI);
    nnK<<<dim3(kH / 128, kBS / 128, 1), 256, GH_SMEM>>>(
        OFF_F1, OFF_CW2, 0, b2, NOBIAS, 0, OFF_T1, 0, kI, kH);
    add_ln_kernel<<<kBS, 256>>>(nullptr, OFF_H1, OFF_T1, g2, be2, out, 0, 0, 0);
}

// round 17
// speedup vs baseline: 1.1711x; 1.1711x over previous
#include <cuda_runtime.h>
#include <cuda_fp16.h>
#include <math.h>
#include <stdint.h>

// ---------------------------------------------------------------------------
// DeBERTa layer, fp16 mma.sync m16n8k16 (fp32 accumulate), ldmatrix fragment
// loads. Uniform K-contiguous layout (A m-major, B n-major). Flash kernel at
// 2 blocks/SM via half gather staging (89KB smem). Strides to gemm_h are HALF
// units. B=16 S=512 H=768 NH=12 DH=64 P=512 I=3072.
// ---------------------------------------------------------------------------

constexpr int kB  = 16;
constexpr int kS  = 512;
constexpr int kH  = 768;
constexpr int kNH = 12;
constexpr int kDH = 64;
constexpr int kP  = 512;
constexpr int kI  = 3072;
constexpr int kBS = kB * kS;
constexpr int kBH = kB * kNH;
constexpr float kScale = 0.07216878364870322f;

constexpr size_t SZ_QKV = (size_t)kBH * kS * kDH;
constexpr size_t SZ_POS = (size_t)kNH * 2 * kP * kDH;
constexpr size_t SZ_CP  = (size_t)kBH * kS * 2 * kP;
constexpr size_t SZ_W   = (size_t)kH * kH;
constexpr size_t SZ_W1  = (size_t)kH * kI;

constexpr size_t OFF_Q    = 0;
constexpr size_t OFF_K    = OFF_Q + SZ_QKV;
constexpr size_t OFF_V    = OFF_K + SZ_QKV;          // V^T layout [z][d][s]
constexpr size_t OFF_PK   = OFF_V + SZ_QKV;
constexpr size_t OFF_PQ   = OFF_PK + SZ_POS;
constexpr size_t OFF_C2P  = OFF_PQ + SZ_POS;
constexpr size_t OFF_P2C  = OFF_C2P + SZ_CP;
constexpr size_t OFF_CTX  = OFF_P2C + SZ_CP;
constexpr size_t OFF_T1   = OFF_CTX + SZ_QKV;        // fp32
constexpr size_t OFF_H1   = OFF_T1 + SZ_QKV;         // fp32 residual
constexpr size_t OFF_H1R  = OFF_H1 + SZ_QKV;         // half (FFN1 A)
constexpr size_t OFF_F1   = OFF_C2P;                 // alias, half
constexpr size_t OFF_CHS  = OFF_H1R + SZ_QKV;        // half
constexpr size_t OFF_CPE  = OFF_CHS + SZ_QKV;        // half
constexpr size_t OFF_CWQ  = OFF_CPE + SZ_POS;        // WT [N][K] half
constexpr size_t OFF_CWK  = OFF_CWQ + SZ_W;
constexpr size_t OFF_CWV  = OFF_CWK + SZ_W;
constexpr size_t OFF_CWPK = OFF_CWV + SZ_W;
constexpr size_t OFF_CWPQ = OFF_CWPK + SZ_W;
constexpr size_t OFF_CWO  = OFF_CWPQ + SZ_W;
constexpr size_t OFF_CW1  = OFF_CWO + SZ_W;
constexpr size_t OFF_CW2  = OFF_CW1 + SZ_W1;
constexpr size_t OFF_CB   = OFF_CW2 + SZ_W1;         // fp32 biases
constexpr size_t TOTAL    = OFF_CB + 3 * kH;

__device__ __align__(256) float g_scratch[TOTAL];

enum { EPI_NONE = 0, EPI_GELU = 1, EPI_QKV = 2, EPI_POS = 3 };
constexpr size_t NOBIAS = (size_t)-1;

__device__ __forceinline__ void mma_f16(float (&d)[4], const uint32_t (&a)[4],
                                        const uint32_t (&b)[2]) {
    asm volatile(
        "mma.sync.aligned.m16n8k16.row.col.f32.f16.f16.f32 "
        "{%0,%1,%2,%3}, {%4,%5,%6,%7}, {%8,%9}, {%0,%1,%2,%3};"
        : "+f"(d[0]), "+f"(d[1]), "+f"(d[2]), "+f"(d[3])
        : "r"(a[0]), "r"(a[1]), "r"(a[2]), "r"(a[3]), "r"(b[0]), "r"(b[1]));
}
__device__ __forceinline__ void ldm_x4(uint32_t (&r)[4], uint32_t addr) {
    asm volatile(
        "ldmatrix.sync.aligned.m8n8.x4.shared.b16 {%0,%1,%2,%3}, [%4];"
        : "=r"(r[0]), "=r"(r[1]), "=r"(r[2]), "=r"(r[3]) : "r"(addr));
}
__device__ __forceinline__ void cp_async16(uint32_t s, const void* g) {
    asm volatile("cp.async.cg.shared.global [%0], [%1], 16;" :: "r"(s), "l"(g));
}
__device__ __forceinline__ void cp_commit() {
    asm volatile("cp.async.commit_group;" ::: "memory");
}
__device__ __forceinline__ void cp_wait1() {
    asm volatile("cp.async.wait_group 1;" ::: "memory");
}
__device__ __forceinline__ void cp_wait0() {
    asm volatile("cp.async.wait_group 0;" ::: "memory");
}
__device__ __forceinline__ uint32_t smem_u32(const void* p) {
    return (uint32_t)__cvta_generic_to_shared(p);
}

// ---------------------------------------------------------------------------
// preconvert: hs/pe -> half; biases contiguous fp32.
// ---------------------------------------------------------------------------
constexpr size_t F4_HS = SZ_QKV / 4;
constexpr size_t F4_PE = SZ_POS / 4;
constexpr size_t F4_TOTAL = F4_HS + F4_PE;

__global__ __launch_bounds__(256)
void preconvert_kernel(const float* __restrict__ hs, const float* __restrict__ pe,
                       const float* __restrict__ bq, const float* __restrict__ bk,
                       const float* __restrict__ bv)
{
    size_t i = (size_t)blockIdx.x * 256 + threadIdx.x;
    if (i < 576) {
        float4* cb = reinterpret_cast<float4*>(g_scratch + OFF_CB);
        if (i < 192)      cb[i] = reinterpret_cast<const float4*>(bq)[i];
        else if (i < 384) cb[i] = reinterpret_cast<const float4*>(bk)[i - 192];
        else              cb[i] = reinterpret_cast<const float4*>(bv)[i - 384];
    }
    if (i >= F4_TOTAL) return;
    const float* src; __half2* dst;
    if (i < F4_HS) { src = hs; dst = reinterpret_cast<__half2*>(g_scratch + OFF_CHS); }
    else { i -= F4_HS; src = pe; dst = reinterpret_cast<__half2*>(g_scratch + OFF_CPE); }
    const float4 v = reinterpret_cast<const float4*>(src)[i];
    dst[i * 2]     = __floats2half2_rn(v.x, v.y);
    dst[i * 2 + 1] = __floats2half2_rn(v.z, v.w);
}

// ---------------------------------------------------------------------------
// transpose weights W[K,N] -> WT[N,K] half. 8064 flat 32x32 tiles.
// ---------------------------------------------------------------------------
__global__ __launch_bounds__(256)
void transpose_kernel(const float* __restrict__ Wq, const float* __restrict__ Wk,
                      const float* __restrict__ Wv, const float* __restrict__ Wpk,
                      const float* __restrict__ Wpq, const float* __restrict__ Wo,
                      const float* __restrict__ W1, const float* __restrict__ W2)
{
    int bid = blockIdx.x;
    const float* src; __half* dst; int R, C, t;
    if (bid < 3456) {
        const float* ws[6] = {Wq, Wk, Wv, Wpk, Wpq, Wo};
        const size_t od[6] = {OFF_CWQ, OFF_CWK, OFF_CWV, OFF_CWPK, OFF_CWPQ, OFF_CWO};
        src = ws[bid / 576]; dst = reinterpret_cast<__half*>(g_scratch + od[bid / 576]);
        R = kH; C = kH; t = bid % 576;
    } else if (bid < 5760) {
        src = W1; dst = reinterpret_cast<__half*>(g_scratch + OFF_CW1);
        R = kH; C = kI; t = bid - 3456;
    } else {
        src = W2; dst = reinterpret_cast<__half*>(g_scratch + OFF_CW2);
        R = kI; C = kH; t = bid - 5760;
    }
    const int n0 = (t % (C / 32)) * 32, k0 = (t / (C / 32)) * 32;
    __shared__ float tl[32][33];
    const int tx = threadIdx.x & 31, ty = threadIdx.x >> 5;
#pragma unroll
    for (int r = ty; r < 32; r += 8)
        tl[r][tx] = src[(size_t)(k0 + r) * C + n0 + tx];
    __syncthreads();
#pragma unroll
    for (int r = ty; r < 32; r += 8)
        dst[(size_t)(n0 + r) * R + k0 + tx] = __float2half_rn(tl[tx][r]);
}

// ---------------------------------------------------------------------------
// Dense fp16 GEMM, ldmatrix fragments (unchanged from R16).
// ---------------------------------------------------------------------------
constexpr int GH_HW  = 20;
constexpr int GH_STG = 128 * GH_HW;
constexpr int GH_SMEM = 6 * GH_STG * 4;

template<int EPI>
__global__ __launch_bounds__(256, 2)
void gemm_h(size_t aOff, size_t bOff, size_t bStride,
            const float* __restrict__ biasEx, size_t biasOff, size_t biasStride,
            size_t cOff, size_t cStride, int K, int Ntot)
{
    extern __shared__ __align__(16) uint32_t dsm[];
    uint32_t* As = dsm;
    uint32_t* Bs = dsm + 3 * GH_STG;

    const int z = blockIdx.z;
    const int m0 = blockIdx.y * 128, n0 = blockIdx.x * 128;
    const int tid = threadIdx.x, warp = tid >> 5, lane = tid & 31;
    const int wm = warp & 3, wn = warp >> 2;
    const int mBase = wm * 32, nBase = wn * 64;
    const int gi = lane >> 2, gj = lane & 3;

    const __half* Ah = reinterpret_cast<const __half*>(g_scratch + aOff)
                     + (size_t)m0 * K;
    const __half* Bh = reinterpret_cast<const __half*>(g_scratch + bOff)
                     + (size_t)z * bStride + (size_t)n0 * K;
    const uint32_t sA = smem_u32(As), sB = smem_u32(Bs);

    const int matIdx = lane >> 3, rowIn = lane & 7;
    int aLdm[2], bLdm[4];
#pragma unroll
    for (int mt = 0; mt < 2; mt++)
        aLdm[mt] = (mBase + mt * 16 + (matIdx & 1) * 8 + rowIn) * GH_HW
                 + (matIdx >> 1) * 4;
#pragma unroll
    for (int p = 0; p < 4; p++)
        bLdm[p] = (nBase + (2 * p + (matIdx >> 1)) * 8 + rowIn) * GH_HW
                + (matIdx & 1) * 4;

    auto load_stage = [&](int st, int kblk) {
#pragma unroll
        for (int i = 0; i < 2; i++) {
            const int idx = tid + i * 256;
            const int row = idx >> 2, g = idx & 3;
            cp_async16(sA + (uint32_t)(st * GH_STG + row * GH_HW + g * 4) * 4,
                       Ah + (size_t)row * K + kblk + g * 8);
            cp_async16(sB + (uint32_t)(st * GH_STG + row * GH_HW + g * 4) * 4,
                       Bh + (size_t)row * K + kblk + g * 8);
        }
    };

    float acc[2][8][4];
#pragma unroll
    for (int i = 0; i < 2; i++)
#pragma unroll
        for (int j = 0; j < 8; j++)
#pragma unroll
            for (int r = 0; r < 4; r++) acc[i][j][r] = 0.f;

    const int NC = K / 32;
    load_stage(0, 0);  cp_commit();
    load_stage(1, 32); cp_commit();

    for (int c = 0; c < NC; c++) {
        cp_wait1();
        __syncthreads();
        if (c + 2 < NC) load_stage((c + 2) % 3, (c + 2) * 32);
        cp_commit();
        const uint32_t stW = (uint32_t)((c % 3) * GH_STG);
#pragma unroll
        for (int ks = 0; ks < 2; ks++) {
            const int kk = ks * 8;
            uint32_t af[2][4], bq[4][4];
            ldm_x4(af[0], sA + (stW + aLdm[0] + kk) * 4);
            ldm_x4(af[1], sA + (stW + aLdm[1] + kk) * 4);
#pragma unroll
            for (int p = 0; p < 4; p++)
                ldm_x4(bq[p], sB + (stW + bLdm[p] + kk) * 4);
#pragma unroll
            for (int mt = 0; mt < 2; mt++)
#pragma unroll
                for (int nt = 0; nt < 8; nt++) {
                    const uint32_t bf[2] = { bq[nt >> 1][(nt & 1) * 2 + 0],
                                             bq[nt >> 1][(nt & 1) * 2 + 1] };
                    mma_f16(acc[mt][nt], af[mt], bf);
                }
        }
    }

    const float* bias = biasEx ? biasEx
                      : (biasOff != NOBIAS ? (const float*)g_scratch + biasOff
                                           : nullptr);
    if (bias) bias += (size_t)z * biasStride;
#pragma unroll
    for (int mt = 0; mt < 2; mt++)
#pragma unroll
        for (int nt = 0; nt < 8; nt++)
#pragma unroll
            for (int hf = 0; hf < 2; hf++) {
                const int m = m0 + mBase + mt * 16 + gi + hf * 8;
                const int n = n0 + nBase + nt * 8 + 2 * gj;
                float v0 = acc[mt][nt][hf * 2 + 0];
                float v1 = acc[mt][nt][hf * 2 + 1];
                if (bias) { v0 += bias[n]; v1 += bias[n + 1]; }
                if constexpr (EPI == EPI_GELU) {
                    v0 = 0.5f * v0 * (1.f + erff(v0 * 0.70710678118654752f));
                    v1 = 0.5f * v1 * (1.f + erff(v1 * 0.70710678118654752f));
                }
                if constexpr (EPI == EPI_NONE) {
                    float* Cf = g_scratch + cOff;
                    *reinterpret_cast<float2*>(&Cf[(size_t)m * Ntot + n]) =
                        make_float2(v0, v1);
                } else {
                    __half* Ch = reinterpret_cast<__half*>(g_scratch + cOff);
                    if constexpr (EPI == EPI_GELU) {
                        *reinterpret_cast<__half2*>(&Ch[(size_t)m * Ntot + n]) =
                            __floats2half2_rn(v0, v1);
                    } else if constexpr (EPI == EPI_QKV) {
                        const int bb = m >> 9, s = m & 511, h = n >> 6, d = n & 63;
                        if (z < 2) {
                            *reinterpret_cast<__half2*>(
                                &Ch[(size_t)z * cStride
                                    + ((size_t)(bb * kNH + h) * kS + s) * kDH + d]) =
                                __floats2half2_rn(v0, v1);
                        } else {   // V^T: [bh][d][s]
                            __half* Vt = Ch + 2 * cStride
                                       + ((size_t)(bb * kNH + h) * kDH + d) * kS + s;
                            Vt[0]  = __float2half_rn(v0);
                            Vt[kS] = __float2half_rn(v1);
                        }
                    } else {       // EPI_POS
                        const int h = n >> 6, d = n & 63;
                        *reinterpret_cast<__half2*>(
                            &Ch[(size_t)z * cStride
                                + ((size_t)h * (2 * kP) + m) * kDH + d]) =
                            __floats2half2_rn(v0, v1);
                    }
                }
            }
}

// ---------------------------------------------------------------------------
// Band GEMM fp16, merged: z < kBH -> Q@PK^T -> C2P; else K@PQ^T -> P2C.
// Diagonal 128x128 tiles, K=64. ldmatrix fragments.
// ---------------------------------------------------------------------------
constexpr int BH_HW = 36;

__global__ __launch_bounds__(256, 2)
void band_gemm_h()
{
    __shared__ __align__(16) uint32_t As[128 * BH_HW], Bs[128 * BH_HW];
    const int zz = blockIdx.z;
    const int z  = (zz < kBH) ? zz : zz - kBH;
    const size_t aOff = (zz < kBH) ? OFF_Q  : OFF_K;
    const size_t bOff = (zz < kBH) ? OFF_PK : OFF_PQ;
    const size_t cOff = (zz < kBH) ? OFF_C2P : OFF_P2C;

    const __half* Ah = reinterpret_cast<const __half*>(g_scratch + aOff)
                     + (size_t)z * kS * kDH;
    const __half* Bh = reinterpret_cast<const __half*>(g_scratch + bOff)
                     + (size_t)(z % kNH) * (2 * kP) * kDH;
    __half* Ch = reinterpret_cast<__half*>(g_scratch + cOff)
               + (size_t)z * kS * (2 * kP);

    const int m0 = blockIdx.y * 128;
    const int n0 = blockIdx.y * 128 + blockIdx.x * 128;
    const int tid = threadIdx.x, warp = tid >> 5, lane = tid & 31;
    const int wm = warp & 3, wn = warp >> 2;
    const int mBase = wm * 32, nBase = wn * 64;
    const int gi = lane >> 2, gj = lane & 3;
    const uint32_t sA = smem_u32(As), sB = smem_u32(Bs);

    const int matIdx = lane >> 3, rowIn = lane & 7;
    int aLdm[2], bLdm[4];
#pragma unroll
    for (int mt = 0; mt < 2; mt++)
        aLdm[mt] = (mBase + mt * 16 + (matIdx & 1) * 8 + rowIn) * BH_HW
                 + (matIdx >> 1) * 4;
#pragma unroll
    for (int p = 0; p < 4; p++)
        bLdm[p] = (nBase + (2 * p + (matIdx >> 1)) * 8 + rowIn) * BH_HW
                + (matIdx & 1) * 4;

#pragma unroll
    for (int i = 0; i < 4; i++) {
        const int idx = tid + i * 256;
        const int row = idx >> 3, g = idx & 7;
        cp_async16(sA + (uint32_t)(row * BH_HW + g * 4) * 4,
                   Ah + (size_t)(m0 + row) * kDH + g * 8);
        cp_async16(sB + (uint32_t)(row * BH_HW + g * 4) * 4,
                   Bh + (size_t)(n0 + row) * kDH + g * 8);
    }
    cp_commit();
    cp_wait0();
    __syncthreads();

    float acc[2][8][4];
#pragma unroll
    for (int i = 0; i < 2; i++)
#pragma unroll
        for (int j = 0; j < 8; j++)
#pragma unroll
            for (int r = 0; r < 4; r++) acc[i][j][r] = 0.f;

#pragma unroll
    for (int ks = 0; ks < 4; ks++) {
        const int kk = ks * 8;
        uint32_t af[2][4], bq[4][4];
        ldm_x4(af[0], sA + (uint32_t)(aLdm[0] + kk) * 4);
        ldm_x4(af[1], sA + (uint32_t)(aLdm[1] + kk) * 4);
#pragma unroll
        for (int p = 0; p < 4; p++)
            ldm_x4(bq[p], sB + (uint32_t)(bLdm[p] + kk) * 4);
#pragma unroll
        for (int mt = 0; mt < 2; mt++)
#pragma unroll
            for (int nt = 0; nt < 8; nt++) {
                const uint32_t bf[2] = { bq[nt >> 1][(nt & 1) * 2 + 0],
                                         bq[nt >> 1][(nt & 1) * 2 + 1] };
                mma_f16(acc[mt][nt], af[mt], bf);
            }
    }
#pragma unroll
    for (int mt = 0; mt < 2; mt++)
#pragma unroll
        for (int nt = 0; nt < 8; nt++)
#pragma unroll
            for (int hf = 0; hf < 2; hf++) {
                const int m = m0 + mBase + mt * 16 + gi + hf * 8;
                const int n = n0 + nBase + nt * 8 + 2 * gj;
                *reinterpret_cast<__half2*>(&Ch[(size_t)m * (2 * kP) + n]) =
                    __floats2half2_rn(acc[mt][nt][hf * 2 + 0],
                                      acc[mt][nt][hf * 2 + 1]);
            }
}

// ---------------------------------------------------------------------------
// Flash attention fp16, 2 blocks/SM: gather staging in HALF (Ph, stride 136
// halves == 68 words; bitwise-identical values vs fp32 staging). P (Pp)
// overlays the same region. smem = 89,088 B.
// ---------------------------------------------------------------------------
constexpr int FH_QS = 0;
constexpr int FH_KS = 128 * 36;
constexpr int FH_VS = 2 * 128 * 36;
constexpr int FH_P  = FH_VS + 64 * 68;
constexpr int FA_SMEM = (FH_P + 128 * 68) * 4;   // 89088 B

__global__ __launch_bounds__(256, 2)
void flash_attn_kernel(const float* __restrict__ mask)
{
    extern __shared__ __align__(16) uint32_t fsm[];
    uint32_t* Qs = fsm + FH_QS;
    uint32_t* Ks = fsm + FH_KS;
    uint32_t* Vs = fsm + FH_VS;
    __half*   Ph = reinterpret_cast<__half*>(fsm + FH_P);   // stride 136 halves
    uint32_t* Pp = fsm + FH_P;                              // stride 68 words

    const int z  = blockIdx.y;
    const int i0 = blockIdx.x * 128;
    const int tid = threadIdx.x, warp = tid >> 5, lane = tid & 31;
    const int gi = lane >> 2, gj = lane & 3;
    const int mBase = warp * 16;

    const __half* Qh = reinterpret_cast<const __half*>(g_scratch + OFF_Q)
                     + (size_t)z * kS * kDH;
    const __half* Kh = reinterpret_cast<const __half*>(g_scratch + OFF_K)
                     + (size_t)z * kS * kDH;
    const __half* Vth = reinterpret_cast<const __half*>(g_scratch + OFF_V)
                      + (size_t)z * kDH * kS;
    const __half* C2Ph = reinterpret_cast<const __half*>(g_scratch + OFF_C2P)
                       + (size_t)z * kS * (2 * kP);
    const __half* P2Ch = reinterpret_cast<const __half*>(g_scratch + OFF_P2C)
                       + (size_t)z * kS * (2 * kP);
    const float* mrow = mask + (size_t)(z / kNH) * kS;

    const uint32_t sQ = smem_u32(Qs), sK = smem_u32(Ks);
    const uint32_t sV = smem_u32(Vs), sP = smem_u32(Pp);
    const int matIdx = lane >> 3, rowIn = lane & 7;
    const int qLdm = (mBase + (matIdx & 1) * 8 + rowIn) * 36 + (matIdx >> 1) * 4;
    const int pLdm = (mBase + (matIdx & 1) * 8 + rowIn) * 68 + (matIdx >> 1) * 4;
    int kLdm[8], vLdm[4];
#pragma unroll
    for (int p = 0; p < 8; p++)
        kLdm[p] = ((2 * p + (matIdx >> 1)) * 8 + rowIn) * 36 + (matIdx & 1) * 4;
#pragma unroll
    for (int p = 0; p < 4; p++)
        vLdm[p] = ((2 * p + (matIdx >> 1)) * 8 + rowIn) * 68 + (matIdx & 1) * 4;

#pragma unroll
    for (int r = 0; r < 4; r++) {
        const int idx = tid + r * 256;
        const int row = idx >> 3, g = idx & 7;
        *reinterpret_cast<uint4*>(&Qs[row * 36 + g * 4]) =
            *reinterpret_cast<const uint4*>(Qh + (size_t)(i0 + row) * kDH + g * 8);
    }

    float ctx[8][4];
#pragma unroll
    for (int n = 0; n < 8; n++)
#pragma unroll
        for (int c = 0; c < 4; c++) ctx[n][c] = 0.f;
    float rm[2] = {-1e30f, -1e30f};
    float rs[2] = {0.f, 0.f};

    for (int jt = 0; jt < 4; jt++) {
        const int j0 = jt * 128;
        __syncthreads();
#pragma unroll
        for (int r = 0; r < 4; r++) {
            const int idx = tid + r * 256;
            const int row = idx >> 3, g = idx & 7;
            *reinterpret_cast<uint4*>(&Ks[row * 36 + g * 4]) =
                *reinterpret_cast<const uint4*>(Kh + (size_t)(j0 + row) * kDH + g * 8);
        }
#pragma unroll
        for (int r = 0; r < 4; r++) {
            const int idx = tid + r * 256;
            const int row = idx >> 4, g = idx & 15;
            *reinterpret_cast<uint4*>(&Vs[row * 68 + g * 4]) =
                *reinterpret_cast<const uint4*>(Vth + (size_t)row * kS + j0 + g * 8);
        }
        __syncthreads();

        // ---- S = Q @ K^T ----
        float accS[16][4];
#pragma unroll
        for (int n = 0; n < 16; n++)
#pragma unroll
            for (int c = 0; c < 4; c++) accS[n][c] = 0.f;
#pragma unroll
        for (int ks = 0; ks < 4; ks++) {
            const int kk = ks * 8;
            uint32_t af[4], bq[8][4];
            ldm_x4(af, sQ + (uint32_t)(qLdm + kk) * 4);
#pragma unroll
            for (int p = 0; p < 8; p++)
                ldm_x4(bq[p], sK + (uint32_t)(kLdm[p] + kk) * 4);
#pragma unroll
            for (int nt = 0; nt < 16; nt++) {
                const uint32_t bf[2] = { bq[nt >> 1][(nt & 1) * 2 + 0],
                                         bq[nt >> 1][(nt & 1) * 2 + 1] };
                mma_f16(accS[nt], af, bf);
            }
        }

        // ---- p2c gather stage (half; bitwise same values) ----
#pragma unroll
        for (int r = 0; r < 64; r++) {
            const int idx = tid + r * 256;
            const int jl = idx >> 7, il = idx & 127;
            Ph[jl * 136 + il] =
                P2Ch[(size_t)(j0 + jl) * (2 * kP) + (j0 + jl) - (i0 + il) + kP];
        }
        __syncthreads();
#pragma unroll
        for (int nt = 0; nt < 16; nt++)
#pragma unroll
            for (int hf = 0; hf < 2; hf++) {
                const int il = mBase + gi + hf * 8;
                const int jl = nt * 8 + 2 * gj;
                accS[nt][hf * 2 + 0] += __half2float(Ph[jl * 136 + il]);
                accS[nt][hf * 2 + 1] += __half2float(Ph[(jl + 1) * 136 + il]);
            }
        __syncthreads();
        // ---- c2p gather stage ----
#pragma unroll
        for (int r = 0; r < 64; r++) {
            const int idx = tid + r * 256;
            const int il = idx >> 7, jl = idx & 127;
            Ph[il * 136 + jl] =
                C2Ph[(size_t)(i0 + il) * (2 * kP) + (i0 + il) - (j0 + jl) + kP];
        }
        __syncthreads();
#pragma unroll
        for (int nt = 0; nt < 16; nt++)
#pragma unroll
            for (int hf = 0; hf < 2; hf++) {
                const int il = mBase + gi + hf * 8;
                const int jl = nt * 8 + 2 * gj;
                float s0 = (accS[nt][hf * 2 + 0]
                            + __half2float(Ph[il * 136 + jl])) * kScale;
                float s1 = (accS[nt][hf * 2 + 1]
                            + __half2float(Ph[il * 136 + jl + 1])) * kScale;
                if (mrow[j0 + jl] <= 0.f)     s0 = -1e9f;
                if (mrow[j0 + jl + 1] <= 0.f) s1 = -1e9f;
                accS[nt][hf * 2 + 0] = s0;
                accS[nt][hf * 2 + 1] = s1;
            }

        // ---- online softmax (rows warp-local, quad shuffles) ----
#pragma unroll
        for (int hf = 0; hf < 2; hf++) {
            float tmax = -1e30f;
#pragma unroll
            for (int nt = 0; nt < 16; nt++)
                tmax = fmaxf(tmax, fmaxf(accS[nt][hf * 2], accS[nt][hf * 2 + 1]));
            tmax = fmaxf(tmax, __shfl_xor_sync(0xFFFFFFFFu, tmax, 1));
            tmax = fmaxf(tmax, __shfl_xor_sync(0xFFFFFFFFu, tmax, 2));
            const float mNew = fmaxf(rm[hf], tmax);
            const float alpha = __expf(rm[hf] - mNew);
            float lsum = 0.f;
#pragma unroll
            for (int nt = 0; nt < 16; nt++) {
                const float e0 = __expf(accS[nt][hf * 2 + 0] - mNew);
                const float e1 = __expf(accS[nt][hf * 2 + 1] - mNew);
                accS[nt][hf * 2 + 0] = e0;
                accS[nt][hf * 2 + 1] = e1;
                lsum += e0 + e1;
            }
            lsum += __shfl_xor_sync(0xFFFFFFFFu, lsum, 1);
            lsum += __shfl_xor_sync(0xFFFFFFFFu, lsum, 2);
            rs[hf] = rs[hf] * alpha + lsum;
            rm[hf] = mNew;
#pragma unroll
            for (int n = 0; n < 8; n++) {
                ctx[n][hf * 2 + 0] *= alpha;
                ctx[n][hf * 2 + 1] *= alpha;
            }
        }

        __syncthreads();
        // ---- write P (half words, m-major, stride 68 words) ----
#pragma unroll
        for (int nt = 0; nt < 16; nt++)
#pragma unroll
            for (int hf = 0; hf < 2; hf++) {
                const int il = mBase + gi + hf * 8;
                const __half2 p = __floats2half2_rn(accS[nt][hf * 2 + 0],
                                                    accS[nt][hf * 2 + 1]);
                Pp[il * 68 + nt * 4 + gj] = *reinterpret_cast<const uint32_t*>(&p);
            }
        __syncthreads();

        // ---- ctx += P @ V ----
#pragma unroll
        for (int ks = 0; ks < 8; ks++) {
            const int kk = ks * 8;
            uint32_t af[4], bq[4][4];
            ldm_x4(af, sP + (uint32_t)(pLdm + kk) * 4);
#pragma unroll
            for (int p = 0; p < 4; p++)
                ldm_x4(bq[p], sV + (uint32_t)(vLdm[p] + kk) * 4);
#pragma unroll
            for (int nt = 0; nt < 8; nt++) {
                const uint32_t bf[2] = { bq[nt >> 1][(nt & 1) * 2 + 0],
                                         bq[nt >> 1][(nt & 1) * 2 + 1] };
                mma_f16(ctx[nt], af, bf);
            }
        }
    }

    const int bb = z / kNH, h = z % kNH;
    const float inv0 = 1.f / rs[0], inv1 = 1.f / rs[1];
    __half* Cg = reinterpret_cast<__half*>(g_scratch + OFF_CTX);
#pragma unroll
    for (int nt = 0; nt < 8; nt++)
#pragma unroll
        for (int hf = 0; hf < 2; hf++) {
            const int m = i0 + mBase + gi + hf * 8;
            const int d = nt * 8 + 2 * gj;
            const float inv = hf ? inv1 : inv0;
            *reinterpret_cast<__half2*>(
                &Cg[((size_t)bb * kS + m) * kH + h * kDH + d]) =
                __floats2half2_rn(ctx[nt][hf * 2 + 0] * inv,
                                  ctx[nt][hf * 2 + 1] * inv);
        }
}

// ---------------------------------------------------------------------------
// out = LayerNorm(X + Y) * g + b; optional half copy for next GEMM.
// ---------------------------------------------------------------------------
__global__ void add_ln_kernel(const float* __restrict__ Xex, size_t xOff, size_t yOff,
                              const float* __restrict__ g, const float* __restrict__ bb,
                              float* __restrict__ outEx, size_t outOff,
                              int makeHalf, size_t rOff)
{
    const float* X = Xex ? Xex : (const float*)g_scratch + xOff;
    const float* Y = (const float*)g_scratch + yOff;
    float* O = outEx ? outEx : g_scratch + outOff;

    const size_t off = (size_t)blockIdx.x * kH;
    const int t = threadIdx.x;
    const float v0 = X[off + t]       + Y[off + t];
    const float v1 = X[off + t + 256] + Y[off + t + 256];
    const float v2 = X[off + t + 512] + Y[off + t + 512];

    __shared__ float red[256];
    red[t] = v0 + v1 + v2;
    __syncthreads();
    for (int s = 128; s > 0; s >>= 1) {
        if (t < s) red[t] += red[t + s];
        __syncthreads();
    }
    const float mean = red[0] * (1.f / 768.f);
    __syncthreads();
    const float d0 = v0 - mean, d1 = v1 - mean, d2 = v2 - mean;
    red[t] = d0 * d0 + d1 * d1 + d2 * d2;
    __syncthreads();
    for (int s = 128; s > 0; s >>= 1) {
        if (t < s) red[t] += red[t + s];
        __syncthreads();
    }
    const float rstd = rsqrtf(red[0] * (1.f / 768.f) + 1e-7f);

    const float o0 = d0 * rstd * g[t]       + bb[t];
    const float o1 = d1 * rstd * g[t + 256] + bb[t + 256];
    const float o2 = d2 * rstd * g[t + 512] + bb[t + 512];
    O[off + t]       = o0;
    O[off + t + 256] = o1;
    O[off + t + 512] = o2;
    if (makeHalf) {
        __half* R = reinterpret_cast<__half*>(g_scratch + rOff);
        R[off + t]       = __float2half_rn(o0);
        R[off + t + 256] = __float2half_rn(o1);
        R[off + t + 512] = __float2half_rn(o2);
    }
}

// ---------------------------------------------------------------------------
extern "C" void kernel_launch(void* const* d_in, const int* in_sizes, int n_in,
                              void* d_out, int out_size)
{
    const float* hs  = (const float*)d_in[0];
    const float* am  = (const float*)d_in[1];
    const float* pe  = (const float*)d_in[2];
    const float* Wq  = (const float*)d_in[3];
    const float* bq  = (const float*)d_in[4];
    const float* Wk  = (const float*)d_in[5];
    const float* bk  = (const float*)d_in[6];
    const float* Wv  = (const float*)d_in[7];
    const float* bv  = (const float*)d_in[8];
    const float* Wpk = (const float*)d_in[9];
    const float* Wpq = (const float*)d_in[10];
    const float* Wo  = (const float*)d_in[11];
    const float* bo  = (const float*)d_in[12];
    const float* g1  = (const float*)d_in[13];
    const float* be1 = (const float*)d_in[14];
    const float* W1  = (const float*)d_in[15];
    const float* b1  = (const float*)d_in[16];
    const float* W2  = (const float*)d_in[17];
    const float* b2  = (const float*)d_in[18];
    const float* g2  = (const float*)d_in[19];
    const float* be2 = (const float*)d_in[20];
    float* out = (float*)d_out;

    auto qkvK = gemm_h<EPI_QKV>;
    auto posK = gemm_h<EPI_POS>;
    auto nnK  = gemm_h<EPI_NONE>;
    auto gelK = gemm_h<EPI_GELU>;
    cudaFuncSetAttribute((const void*)qkvK, cudaFuncAttributeMaxDynamicSharedMemorySize, GH_SMEM);
    cudaFuncSetAttribute((const void*)posK, cudaFuncAttributeMaxDynamicSharedMemorySize, GH_SMEM);
    cudaFuncSetAttribute((const void*)nnK,  cudaFuncAttributeMaxDynamicSharedMemorySize, GH_SMEM);
    cudaFuncSetAttribute((const void*)gelK, cudaFuncAttributeMaxDynamicSharedMemorySize, GH_SMEM);
    cudaFuncSetAttribute((const void*)flash_attn_kernel,
                         cudaFuncAttributeMaxDynamicSharedMemorySize, FA_SMEM);

    preconvert_kernel<<<(int)((F4_TOTAL + 255) / 256), 256>>>(hs, pe, bq, bk, bv);
    transpose_kernel<<<8064, 256>>>(Wq, Wk, Wv, Wpk, Wpq, Wo, W1, W2);

    qkvK<<<dim3(kH / 128, kBS / 128, 3), 256, GH_SMEM>>>(
        OFF_CHS, OFF_CWQ, 2 * SZ_W, nullptr, OFF_CB, kH, OFF_Q, 2 * SZ_QKV, kH, kH);
    posK<<<dim3(kH / 128, (2 * kP) / 128, 2), 256, GH_SMEM>>>(
        OFF_CPE, OFF_CWPK, 2 * SZ_W, nullptr, NOBIAS, 0, OFF_PK, 2 * SZ_POS, kH, kH);

    // merged band GEMMs: z<kBH -> c2p, else p2c
    band_gemm_h<<<dim3(5, kS / 128, 2 * kBH), 256>>>();

    flash_attn_kernel<<<dim3(kS / 128, kBH), 256, FA_SMEM>>>(am);

    nnK<<<dim3(kH / 128, kBS / 128, 1), 256, GH_SMEM>>>(
        OFF_CTX, OFF_CWO, 0, bo, NOBIAS, 0, OFF_T1, 0, kH, kH);
    add_ln_kernel<<<kBS, 256>>>(hs, 0, OFF_T1, g1, be1, nullptr, OFF_H1, 1, OFF_H1R);

    gelK<<<dim3(kI / 128, kBS / 128, 1), 256, GH_SMEM>>>(
        OFF_H1R, OFF_CW1, 0, b1, NOBIAS, 0, OFF_F1, 0, kH, kI);
    nnK<<<dim3(kH / 128, kBS / 128, 1), 256, GH_SMEM>>>(
        OFF_F1, OFF_CW2, 0, b2, NOBIAS, 0, OFF_T1, 0, kI, kH);
    add_ln_kernel<<<kBS, 256>>>(nullptr, OFF_H1, OFF_T1, g2, be2, out, 0, 0, 0);
}